// round 10
// baseline (speedup 1.0000x reference)
#include <cuda_runtime.h>
#include <cstdint>
#include <cstddef>

// ---------------- problem constants ----------------
#define E_LOC   8
#define B_DIM   4
#define C_CAP   1024
#define D_MODEL 1024
#define D_FF    4096

// ---------------- tile config ----------------
// Block tile 128(M) x 128(N) x 32(K), 256 threads = 8 warps in 2(M) x 4(N),
// warp tile 64x32 = 4x4 fragments of mma.sync.m16n8k8.tf32. 3-stage cp.async.
// 2 CTAs per SM (reg cap 128, smem 110,592/CTA) so one CTA's memory phase
// overlaps the other's tensor phase.
#define BM 128
#define BN 128
#define BK 32
#define STAGES 3

#define PAD_LD      36                      // floats per row (32 data + 4 pad)
#define A_FLOATS    (BM * PAD_LD)           // 4608
#define B_FLOATS    (BN * PAD_LD)           // 4608
#define STG_FLOATS  (A_FLOATS + B_FLOATS)   // 9216
#define SMEM_BYTES  (STAGES * STG_FLOATS * 4)   // 110592

// ---------------- scratch (static __device__: no runtime alloc) ----------------
__device__ float g_hidden[(size_t)B_DIM * E_LOC * C_CAP * D_FF];   // 512 MB
__device__ float g_xr [(size_t)B_DIM * E_LOC * C_CAP * D_MODEL];   // 128 MB
__device__ float g_w1r[(size_t)E_LOC * D_FF * D_MODEL];            // 128 MB
__device__ float g_w2r[(size_t)E_LOC * D_MODEL * D_FF];            // 128 MB

// ---------------- helpers ----------------
__device__ __forceinline__ float rna_tf32(float x) {
    uint32_t u;
    asm("cvt.rna.tf32.f32 %0, %1;" : "=r"(u) : "f"(x));
    return __uint_as_float(u);
}
__device__ __forceinline__ uint32_t smem_u32(const void* p) {
    uint32_t a;
    asm("{ .reg .u64 t; cvta.to.shared.u64 t, %1; cvt.u32.u64 %0, t; }" : "=r"(a) : "l"(p));
    return a;
}
__device__ __forceinline__ void cp_async16(uint32_t saddr, const void* g) {
    asm volatile("cp.async.cg.shared.global [%0], [%1], 16;" :: "r"(saddr), "l"(g));
}
#define CP_COMMIT() asm volatile("cp.async.commit_group;" ::: "memory")
#define CP_WAIT1()  asm volatile("cp.async.wait_group 1;" ::: "memory")

__device__ __forceinline__ float gelu_exact(float x) {
    return 0.5f * x * (1.0f + erff(x * 0.7071067811865476f));
}

// ---------------- stage loader: gmem -> padded smem via cp.async ----------------
// A: 128 rows x 32 floats (8x16B chunks/row); B: 128 rows x 32 floats.
__device__ __forceinline__ void load_stage(uint32_t sbase, int buf, int kt,
                                           const float* __restrict__ Ab,
                                           const float* __restrict__ Bb,
                                           int K, int tid)
{
    const int k0 = kt * BK;
    const uint32_t abase = sbase + (uint32_t)buf * (STG_FLOATS * 4);
    const uint32_t bbase = abase + A_FLOATS * 4;
#pragma unroll
    for (int i = 0; i < 4; i++) {               // 1024 A-chunks / 256 threads
        int idx = i * 256 + tid;
        int r = idx >> 3, j = idx & 7;
        cp_async16(abase + r * (PAD_LD * 4) + j * 16, Ab + (size_t)r * K + k0 + j * 4);
    }
#pragma unroll
    for (int i = 0; i < 4; i++) {               // 1024 B-chunks / 256 threads
        int idx = i * 256 + tid;
        int r = idx >> 3, j = idx & 7;
        cp_async16(bbase + r * (PAD_LD * 4) + j * 16, Bb + (size_t)r * K + k0 + j * 4);
    }
}

// ---------------- grouped NT GEMM: C = A @ B^T (+bias)(+GELU) -----------------
// Inputs MUST already be tf32-representable (rna-pre-rounded): the mainloop
// feeds raw f32 bits to mma.sync.tf32 with no per-element cvt.
template <bool GELU>
__global__ __launch_bounds__(256, 2)
void gemm_nt_tf32(const float* __restrict__ A, const float* __restrict__ Bw,
                  const float* __restrict__ bias, float* __restrict__ C,
                  int K, int ldc, size_t a_zstr, size_t b_estr, int bias_n, size_t c_zstr)
{
    extern __shared__ float smem[];

    const int tid  = threadIdx.x;
    const int lane = tid & 31;
    const int warp = tid >> 5;
    const int wm   = warp >> 2;   // 0..1 -> rows wm*64
    const int wn   = warp & 3;    // 0..3 -> cols wn*32

    const int z = blockIdx.z;
    const int e = z & (E_LOC - 1);

    const float* Ab    = A    + (size_t)z * a_zstr + (size_t)blockIdx.y * BM * K;
    const float* Bb    = Bw   + (size_t)e * b_estr + (size_t)blockIdx.x * BN * K;
    const float* biasb = bias + (size_t)e * bias_n + (size_t)blockIdx.x * BN;
    float*       Cb    = C    + (size_t)z * c_zstr + (size_t)blockIdx.y * BM * ldc
                              + (size_t)blockIdx.x * BN;

    const uint32_t sbase = smem_u32(smem);

    float acc[4][4][4];
#pragma unroll
    for (int mt = 0; mt < 4; mt++)
#pragma unroll
        for (int nt = 0; nt < 4; nt++)
#pragma unroll
            for (int i = 0; i < 4; i++) acc[mt][nt][i] = 0.0f;

    const int NK = K >> 5;

    // prologue: stages 0,1
    load_stage(sbase, 0, 0, Ab, Bb, K, tid); CP_COMMIT();
    load_stage(sbase, 1, 1, Ab, Bb, K, tid); CP_COMMIT();

#pragma unroll 1
    for (int kt = 0; kt < NK; ++kt) {
        CP_WAIT1();                 // stage kt resident
        __syncthreads();            // all warps done reading the buffer being refilled

        if (kt + 2 < NK)
            load_stage(sbase, (kt + 2) % 3, kt + 2, Ab, Bb, K, tid);
        CP_COMMIT();                // empty commit keeps group accounting uniform

        const float* As = smem + (kt % 3) * STG_FLOATS;
        const float* Bs = As + A_FLOATS;

#pragma unroll
        for (int kk = 0; kk < 4; kk++) {
            const int c = kk * 8 + (lane & 3);
            uint32_t af[4][4];
#pragma unroll
            for (int mt = 0; mt < 4; mt++) {
                const int r = wm * 64 + mt * 16 + (lane >> 2);
                af[mt][0] = __float_as_uint(As[r * PAD_LD + c]);
                af[mt][1] = __float_as_uint(As[(r + 8) * PAD_LD + c]);
                af[mt][2] = __float_as_uint(As[r * PAD_LD + c + 4]);
                af[mt][3] = __float_as_uint(As[(r + 8) * PAD_LD + c + 4]);
            }
#pragma unroll
            for (int nt = 0; nt < 4; nt++) {
                const int r = wn * 32 + nt * 8 + (lane >> 2);
                uint32_t b0 = __float_as_uint(Bs[r * PAD_LD + c]);
                uint32_t b1 = __float_as_uint(Bs[r * PAD_LD + c + 4]);
#pragma unroll
                for (int mt = 0; mt < 4; mt++) {
                    asm volatile(
                        "mma.sync.aligned.m16n8k8.row.col.f32.tf32.tf32.f32 "
                        "{%0,%1,%2,%3},{%4,%5,%6,%7},{%8,%9},{%0,%1,%2,%3};"
                        : "+f"(acc[mt][nt][0]), "+f"(acc[mt][nt][1]),
                          "+f"(acc[mt][nt][2]), "+f"(acc[mt][nt][3])
                        : "r"(af[mt][0]), "r"(af[mt][1]), "r"(af[mt][2]), "r"(af[mt][3]),
                          "r"(b0), "r"(b1));
                }
            }
        }
    }

    // ---------------- epilogue: bias (+GELU, rna-rounded for GEMM2 input) ----------------
#pragma unroll
    for (int mt = 0; mt < 4; mt++) {
        const int r0 = wm * 64 + mt * 16 + (lane >> 2);
#pragma unroll
        for (int nt = 0; nt < 4; nt++) {
            const int c0 = wn * 32 + nt * 8 + 2 * (lane & 3);
            const float b0 = biasb[c0];
            const float b1 = biasb[c0 + 1];
            float v0 = acc[mt][nt][0] + b0;
            float v1 = acc[mt][nt][1] + b1;
            float v2 = acc[mt][nt][2] + b0;
            float v3 = acc[mt][nt][3] + b1;
            if (GELU) {
                v0 = rna_tf32(gelu_exact(v0));
                v1 = rna_tf32(gelu_exact(v1));
                v2 = rna_tf32(gelu_exact(v2));
                v3 = rna_tf32(gelu_exact(v3));
            }
            *reinterpret_cast<float2*>(Cb + (size_t)r0 * ldc + c0)       = make_float2(v0, v1);
            *reinterpret_cast<float2*>(Cb + (size_t)(r0 + 8) * ldc + c0) = make_float2(v2, v3);
        }
    }
}

// ---------------- prepass: rna-round fp32 -> tf32-representable fp32 ----------------
__global__ void rna_round_kernel(const float4* __restrict__ in, float4* __restrict__ out,
                                 size_t n4)
{
    size_t i = (size_t)blockIdx.x * blockDim.x + threadIdx.x;
    const size_t stride = (size_t)gridDim.x * blockDim.x;
    for (; i < n4; i += stride) {
        float4 v = in[i];
        v.x = rna_tf32(v.x); v.y = rna_tf32(v.y);
        v.z = rna_tf32(v.z); v.w = rna_tf32(v.w);
        out[i] = v;
    }
}

// ---------------- launch ----------------
extern "C" void kernel_launch(void* const* d_in, const int* in_sizes, int n_in,
                              void* d_out, int out_size)
{
    const float* x  = (const float*)d_in[0];  // [B, E*C, D]
    const float* w1 = (const float*)d_in[1];  // [E, F, D]
    const float* b1 = (const float*)d_in[2];  // [E, F]
    const float* w2 = (const float*)d_in[3];  // [E, D, F]
    const float* b2 = (const float*)d_in[4];  // [E, D]
    float* out = (float*)d_out;               // [B, E*C, D]

    float *h, *xr, *w1r, *w2r;
    cudaGetSymbolAddress((void**)&h,   g_hidden);
    cudaGetSymbolAddress((void**)&xr,  g_xr);
    cudaGetSymbolAddress((void**)&w1r, g_w1r);
    cudaGetSymbolAddress((void**)&w2r, g_w2r);

    cudaFuncSetAttribute(gemm_nt_tf32<true>,  cudaFuncAttributeMaxDynamicSharedMemorySize, SMEM_BYTES);
    cudaFuncSetAttribute(gemm_nt_tf32<false>, cudaFuncAttributeMaxDynamicSharedMemorySize, SMEM_BYTES);

    const size_t nx = (size_t)B_DIM * E_LOC * C_CAP * D_MODEL;  // 32M
    const size_t nw = (size_t)E_LOC * D_FF * D_MODEL;           // 32M
    rna_round_kernel<<<2048, 256>>>((const float4*)x,  (float4*)xr,  nx / 4);
    rna_round_kernel<<<2048, 256>>>((const float4*)w1, (float4*)w1r, nw / 4);
    rna_round_kernel<<<2048, 256>>>((const float4*)w2, (float4*)w2r, nw / 4);

    const int ZB = B_DIM * E_LOC;  // 32

    // GEMM1: hidden = gelu_rna(x @ w1^T + b1)   M=1024, N=4096, K=1024
    {
        dim3 grid(D_FF / BN, C_CAP / BM, ZB);   // (32, 8, 32)
        gemm_nt_tf32<true><<<grid, 256, SMEM_BYTES>>>(
            xr, w1r, b1, h,
            /*K=*/D_MODEL, /*ldc=*/D_FF,
            /*a_zstr=*/(size_t)C_CAP * D_MODEL,
            /*b_estr=*/(size_t)D_FF * D_MODEL,
            /*bias_n=*/D_FF,
            /*c_zstr=*/(size_t)C_CAP * D_FF);
    }

    // GEMM2: out = hidden @ w2^T + b2           M=1024, N=1024, K=4096
    {
        dim3 grid(D_MODEL / BN, C_CAP / BM, ZB);  // (8, 8, 32)
        gemm_nt_tf32<false><<<grid, 256, SMEM_BYTES>>>(
            h, w2r, b2, out,
            /*K=*/D_FF, /*ldc=*/D_MODEL,
            /*a_zstr=*/(size_t)C_CAP * D_FF,
            /*b_estr=*/(size_t)D_MODEL * D_FF,
            /*bias_n=*/D_MODEL,
            /*c_zstr=*/(size_t)C_CAP * D_MODEL);
    }
}

// round 11
// speedup vs baseline: 1.6505x; 1.6505x over previous
#include <cuda_runtime.h>
#include <cuda_fp16.h>
#include <cstdint>
#include <cstddef>

// ---------------- problem constants ----------------
#define E_LOC   8
#define B_DIM   4
#define C_CAP   1024
#define D_MODEL 1024
#define D_FF    4096

// ---------------- tile config ----------------
// fp16 HMMA (full-rate pipe, 10-bit mantissa == tf32 precision, fp32 accum).
// Block tile 128(M) x 128(N) x 32(K), 256 threads = 8 warps in 2(M) x 4(N),
// warp tile 64x32 = 4x4 fragments of mma.sync.m16n8k16. 3-stage cp.async,
// 2 CTAs/SM (smem 60KB/CTA, regs <=128).
#define BM 128
#define BN 128
#define BK 32
#define STAGES 3

#define PAD_LD      40                      // halves per row (32 data + 8 pad = 80B)
#define A_HALVES    (BM * PAD_LD)           // 5120
#define B_HALVES    (BN * PAD_LD)           // 5120
#define STG_HALVES  (A_HALVES + B_HALVES)   // 10240
#define SMEM_BYTES  (STAGES * STG_HALVES * 2)   // 61440

// ---------------- scratch (static __device__: no runtime alloc) ----------------
__device__ __half g_hid[(size_t)B_DIM * E_LOC * C_CAP * D_FF];     // 256 MB
__device__ __half g_xh [(size_t)B_DIM * E_LOC * C_CAP * D_MODEL];  // 64 MB
__device__ __half g_w1h[(size_t)E_LOC * D_FF * D_MODEL];           // 64 MB
__device__ __half g_w2h[(size_t)E_LOC * D_MODEL * D_FF];           // 64 MB

// ---------------- helpers ----------------
__device__ __forceinline__ uint32_t smem_u32(const void* p) {
    uint32_t a;
    asm("{ .reg .u64 t; cvta.to.shared.u64 t, %1; cvt.u32.u64 %0, t; }" : "=r"(a) : "l"(p));
    return a;
}
__device__ __forceinline__ void cp_async16(uint32_t saddr, const void* g) {
    asm volatile("cp.async.cg.shared.global [%0], [%1], 16;" :: "r"(saddr), "l"(g));
}
#define CP_COMMIT() asm volatile("cp.async.commit_group;" ::: "memory")
#define CP_WAIT1()  asm volatile("cp.async.wait_group 1;" ::: "memory")

__device__ __forceinline__ float gelu_exact(float x) {
    return 0.5f * x * (1.0f + erff(x * 0.7071067811865476f));
}
__device__ __forceinline__ uint32_t h2_to_u32(__half2 h) {
    return *reinterpret_cast<uint32_t*>(&h);
}

// ---------------- stage loader: gmem(half) -> padded smem via cp.async ----------------
// A: 128 rows x 32 halves (4x16B chunks/row); B: 128 rows x 32 halves.
__device__ __forceinline__ void load_stage(uint32_t sbase, int buf, int kt,
                                           const __half* __restrict__ Ab,
                                           const __half* __restrict__ Bb,
                                           int K, int tid)
{
    const int k0 = kt * BK;
    const uint32_t abase = sbase + (uint32_t)buf * (STG_HALVES * 2);
    const uint32_t bbase = abase + A_HALVES * 2;
#pragma unroll
    for (int i = 0; i < 2; i++) {               // 512 A-chunks / 256 threads
        int idx = i * 256 + tid;
        int r = idx >> 2, j = idx & 3;
        cp_async16(abase + r * (PAD_LD * 2) + j * 16, Ab + (size_t)r * K + k0 + j * 8);
    }
#pragma unroll
    for (int i = 0; i < 2; i++) {               // 512 B-chunks / 256 threads
        int idx = i * 256 + tid;
        int r = idx >> 2, j = idx & 3;
        cp_async16(bbase + r * (PAD_LD * 2) + j * 16, Bb + (size_t)r * K + k0 + j * 8);
    }
}

// ---------------- grouped NT GEMM: C = A @ B^T (+bias)(+GELU) -----------------
// A [.., M, K] K-contig half; Bw [e, N, K] K-contig half.
// GELU=true: writes __half hidden. GELU=false: writes float.
template <bool GELU>
__global__ __launch_bounds__(256, 2)
void gemm_nt_f16(const __half* __restrict__ A, const __half* __restrict__ Bw,
                 const float* __restrict__ bias, void* __restrict__ Cv,
                 int K, int ldc, size_t a_zstr, size_t b_estr, int bias_n, size_t c_zstr)
{
    extern __shared__ __half smem[];

    const int tid  = threadIdx.x;
    const int lane = tid & 31;
    const int warp = tid >> 5;
    const int wm   = warp >> 2;   // 0..1 -> rows wm*64
    const int wn   = warp & 3;    // 0..3 -> cols wn*32

    const int z = blockIdx.z;
    const int e = z & (E_LOC - 1);

    const __half* Ab   = A    + (size_t)z * a_zstr + (size_t)blockIdx.y * BM * K;
    const __half* Bb   = Bw   + (size_t)e * b_estr + (size_t)blockIdx.x * BN * K;
    const float* biasb = bias + (size_t)e * bias_n + (size_t)blockIdx.x * BN;
    const size_t cbase = (size_t)z * c_zstr + (size_t)blockIdx.y * BM * ldc
                       + (size_t)blockIdx.x * BN;

    const uint32_t sbase = smem_u32(smem);

    float acc[4][4][4];
#pragma unroll
    for (int mt = 0; mt < 4; mt++)
#pragma unroll
        for (int nt = 0; nt < 4; nt++)
#pragma unroll
            for (int i = 0; i < 4; i++) acc[mt][nt][i] = 0.0f;

    const int NK = K >> 5;

    load_stage(sbase, 0, 0, Ab, Bb, K, tid); CP_COMMIT();
    load_stage(sbase, 1, 1, Ab, Bb, K, tid); CP_COMMIT();

#pragma unroll 1
    for (int kt = 0; kt < NK; ++kt) {
        CP_WAIT1();                 // stage kt resident
        __syncthreads();            // all warps done reading the buffer being refilled

        if (kt + 2 < NK)
            load_stage(sbase, (kt + 2) % 3, kt + 2, Ab, Bb, K, tid);
        CP_COMMIT();                // empty commit keeps group accounting uniform

        const uint32_t* Au = reinterpret_cast<const uint32_t*>(smem + (kt % 3) * STG_HALVES);
        const uint32_t* Bu = Au + (A_HALVES >> 1);

#pragma unroll
        for (int ks = 0; ks < 2; ks++) {        // two K=16 steps per 32-K tile
            const int c = ks * 16 + 2 * (lane & 3);   // half index, even
            uint32_t af[4][4];
#pragma unroll
            for (int mt = 0; mt < 4; mt++) {
                const int r = wm * 64 + mt * 16 + (lane >> 2);
                const int i0 = (r * PAD_LD + c) >> 1;
                af[mt][0] = Au[i0];                          // (r,   k0..k0+1)
                af[mt][1] = Au[i0 + (8 * PAD_LD >> 1)];      // (r+8, k0..k0+1)
                af[mt][2] = Au[i0 + 4];                      // (r,   k0+8..9)
                af[mt][3] = Au[i0 + (8 * PAD_LD >> 1) + 4];  // (r+8, k0+8..9)
            }
#pragma unroll
            for (int nt = 0; nt < 4; nt++) {
                const int n = wn * 32 + nt * 8 + (lane >> 2);
                const int j0 = (n * PAD_LD + c) >> 1;
                uint32_t b0 = Bu[j0];
                uint32_t b1 = Bu[j0 + 4];
#pragma unroll
                for (int mt = 0; mt < 4; mt++) {
                    asm volatile(
                        "mma.sync.aligned.m16n8k16.row.col.f32.f16.f16.f32 "
                        "{%0,%1,%2,%3},{%4,%5,%6,%7},{%8,%9},{%0,%1,%2,%3};"
                        : "+f"(acc[mt][nt][0]), "+f"(acc[mt][nt][1]),
                          "+f"(acc[mt][nt][2]), "+f"(acc[mt][nt][3])
                        : "r"(af[mt][0]), "r"(af[mt][1]), "r"(af[mt][2]), "r"(af[mt][3]),
                          "r"(b0), "r"(b1));
                }
            }
        }
    }

    // ---------------- epilogue ----------------
#pragma unroll
    for (int mt = 0; mt < 4; mt++) {
        const int r0 = wm * 64 + mt * 16 + (lane >> 2);
#pragma unroll
        for (int nt = 0; nt < 4; nt++) {
            const int c0 = wn * 32 + nt * 8 + 2 * (lane & 3);
            const float b0 = biasb[c0];
            const float b1 = biasb[c0 + 1];
            float v0 = acc[mt][nt][0] + b0;
            float v1 = acc[mt][nt][1] + b1;
            float v2 = acc[mt][nt][2] + b0;
            float v3 = acc[mt][nt][3] + b1;
            if (GELU) {
                __half* Ch = (__half*)Cv + cbase;
                __half2 p0 = __floats2half2_rn(gelu_exact(v0), gelu_exact(v1));
                __half2 p1 = __floats2half2_rn(gelu_exact(v2), gelu_exact(v3));
                *reinterpret_cast<__half2*>(Ch + (size_t)r0 * ldc + c0)       = p0;
                *reinterpret_cast<__half2*>(Ch + (size_t)(r0 + 8) * ldc + c0) = p1;
            } else {
                float* Cf = (float*)Cv + cbase;
                *reinterpret_cast<float2*>(Cf + (size_t)r0 * ldc + c0)       = make_float2(v0, v1);
                *reinterpret_cast<float2*>(Cf + (size_t)(r0 + 8) * ldc + c0) = make_float2(v2, v3);
            }
        }
    }
}

// ---------------- prepass: fp32 -> fp16 (rn) ----------------
__global__ void f2h_kernel(const float4* __restrict__ in, uint4* __restrict__ out, size_t n8)
{
    size_t i = (size_t)blockIdx.x * blockDim.x + threadIdx.x;
    const size_t stride = (size_t)gridDim.x * blockDim.x;
    for (; i < n8; i += stride) {
        float4 a = in[2 * i];
        float4 b = in[2 * i + 1];
        uint4 o;
        o.x = h2_to_u32(__floats2half2_rn(a.x, a.y));
        o.y = h2_to_u32(__floats2half2_rn(a.z, a.w));
        o.z = h2_to_u32(__floats2half2_rn(b.x, b.y));
        o.w = h2_to_u32(__floats2half2_rn(b.z, b.w));
        out[i] = o;
    }
}

// ---------------- launch ----------------
extern "C" void kernel_launch(void* const* d_in, const int* in_sizes, int n_in,
                              void* d_out, int out_size)
{
    const float* x  = (const float*)d_in[0];  // [B, E*C, D]
    const float* w1 = (const float*)d_in[1];  // [E, F, D]
    const float* b1 = (const float*)d_in[2];  // [E, F]
    const float* w2 = (const float*)d_in[3];  // [E, D, F]
    const float* b2 = (const float*)d_in[4];  // [E, D]
    float* out = (float*)d_out;               // [B, E*C, D]

    __half *hid, *xh, *w1h, *w2h;
    cudaGetSymbolAddress((void**)&hid, g_hid);
    cudaGetSymbolAddress((void**)&xh,  g_xh);
    cudaGetSymbolAddress((void**)&w1h, g_w1h);
    cudaGetSymbolAddress((void**)&w2h, g_w2h);

    cudaFuncSetAttribute(gemm_nt_f16<true>,  cudaFuncAttributeMaxDynamicSharedMemorySize, SMEM_BYTES);
    cudaFuncSetAttribute(gemm_nt_f16<false>, cudaFuncAttributeMaxDynamicSharedMemorySize, SMEM_BYTES);

    const size_t nx = (size_t)B_DIM * E_LOC * C_CAP * D_MODEL;  // 32M
    const size_t nw = (size_t)E_LOC * D_FF * D_MODEL;           // 32M
    f2h_kernel<<<2048, 256>>>((const float4*)x,  (uint4*)xh,  nx / 8);
    f2h_kernel<<<2048, 256>>>((const float4*)w1, (uint4*)w1h, nw / 8);
    f2h_kernel<<<2048, 256>>>((const float4*)w2, (uint4*)w2h, nw / 8);

    const int ZB = B_DIM * E_LOC;  // 32

    // GEMM1: hid = half(gelu(x @ w1^T + b1))   M=1024, N=4096, K=1024
    {
        dim3 grid(D_FF / BN, C_CAP / BM, ZB);   // (32, 8, 32)
        gemm_nt_f16<true><<<grid, 256, SMEM_BYTES>>>(
            xh, w1h, b1, hid,
            /*K=*/D_MODEL, /*ldc=*/D_FF,
            /*a_zstr=*/(size_t)C_CAP * D_MODEL,
            /*b_estr=*/(size_t)D_FF * D_MODEL,
            /*bias_n=*/D_FF,
            /*c_zstr=*/(size_t)C_CAP * D_FF);
    }

    // GEMM2: out = hid @ w2^T + b2             M=1024, N=1024, K=4096
    {
        dim3 grid(D_MODEL / BN, C_CAP / BM, ZB);  // (8, 8, 32)
        gemm_nt_f16<false><<<grid, 256, SMEM_BYTES>>>(
            hid, w2h, b2, out,
            /*K=*/D_FF, /*ldc=*/D_MODEL,
            /*a_zstr=*/(size_t)C_CAP * D_FF,
            /*b_estr=*/(size_t)D_MODEL * D_FF,
            /*bias_n=*/D_MODEL,
            /*c_zstr=*/(size_t)C_CAP * D_MODEL);
    }
}

// round 14
// speedup vs baseline: 1.9110x; 1.1578x over previous
#include <cuda_runtime.h>
#include <cuda_fp16.h>
#include <cstdint>
#include <cstddef>

// ---------------- problem constants ----------------
#define E_LOC   8
#define B_DIM   4
#define C_CAP   1024
#define D_MODEL 1024
#define D_FF    4096

// ---------------- tile config ----------------
// fp16 HMMA m16n8k16, fp32 accum. Block 128x128x32, 256 thr = 8 warps (2M x 4N),
// warp tile 64x32. Fragments fed by ldmatrix.m8n8.x4 (LDSM), 3-stage cp.async,
// 2 CTAs/SM.
#define BM 128
#define BN 128
#define BK 32
#define STAGES 3

#define PAD_LD      40                      // halves per row (80B): LDSM conflict-free
#define A_HALVES    (BM * PAD_LD)           // 5120
#define B_HALVES    (BN * PAD_LD)           // 5120
#define STG_HALVES  (A_HALVES + B_HALVES)   // 10240
#define STG_BYTES   (STG_HALVES * 2)
#define SMEM_BYTES  (STAGES * STG_BYTES)    // 61440

// ---------------- scratch (static __device__: no runtime alloc) ----------------
__device__ __half g_hid[(size_t)B_DIM * E_LOC * C_CAP * D_FF];     // 256 MB
__device__ __half g_xh [(size_t)B_DIM * E_LOC * C_CAP * D_MODEL];  // 64 MB
__device__ __half g_w1h[(size_t)E_LOC * D_FF * D_MODEL];           // 64 MB
__device__ __half g_w2h[(size_t)E_LOC * D_MODEL * D_FF];           // 64 MB

// ---------------- helpers ----------------
__device__ __forceinline__ uint32_t smem_u32(const void* p) {
    uint32_t a;
    asm("{ .reg .u64 t; cvta.to.shared.u64 t, %1; cvt.u32.u64 %0, t; }" : "=r"(a) : "l"(p));
    return a;
}
__device__ __forceinline__ void cp_async16(uint32_t saddr, const void* g) {
    asm volatile("cp.async.cg.shared.global [%0], [%1], 16;" :: "r"(saddr), "l"(g));
}
#define CP_COMMIT() asm volatile("cp.async.commit_group;" ::: "memory")
#define CP_WAIT1()  asm volatile("cp.async.wait_group 1;" ::: "memory")

__device__ __forceinline__ void ldsm_x4(uint32_t* r, uint32_t addr) {
    asm volatile("ldmatrix.sync.aligned.m8n8.x4.shared.b16 {%0,%1,%2,%3}, [%4];"
                 : "=r"(r[0]), "=r"(r[1]), "=r"(r[2]), "=r"(r[3]) : "r"(addr));
}
__device__ __forceinline__ float gelu_exact(float x) {
    return 0.5f * x * (1.0f + erff(x * 0.7071067811865476f));
}
__device__ __forceinline__ uint32_t h2_to_u32(__half2 h) {
    return *reinterpret_cast<uint32_t*>(&h);
}

// ---------------- stage loader: gmem(half) -> padded smem via cp.async ----------------
__device__ __forceinline__ void load_stage(uint32_t sbase, int buf, int kt,
                                           const __half* __restrict__ Ab,
                                           const __half* __restrict__ Bb,
                                           int K, int tid)
{
    const int k0 = kt * BK;
    const uint32_t abase = sbase + (uint32_t)buf * STG_BYTES;
    const uint32_t bbase = abase + A_HALVES * 2;
#pragma unroll
    for (int i = 0; i < 2; i++) {               // 512 A-chunks / 256 threads
        int idx = i * 256 + tid;
        int r = idx >> 2, j = idx & 3;
        cp_async16(abase + r * (PAD_LD * 2) + j * 16, Ab + (size_t)r * K + k0 + j * 8);
    }
#pragma unroll
    for (int i = 0; i < 2; i++) {               // 512 B-chunks / 256 threads
        int idx = i * 256 + tid;
        int r = idx >> 2, j = idx & 3;
        cp_async16(bbase + r * (PAD_LD * 2) + j * 16, Bb + (size_t)r * K + k0 + j * 8);
    }
}

// ---------------- grouped NT GEMM: C = A @ B^T (+bias)(+GELU) -----------------
// GELU=true writes __half hidden; GELU=false writes float.
template <bool GELU>
__global__ __launch_bounds__(256, 2)
void gemm_nt_f16(const __half* __restrict__ A, const __half* __restrict__ Bw,
                 const float* __restrict__ bias, void* __restrict__ Cv,
                 int K, int ldc, size_t a_zstr, size_t b_estr, int bias_n, size_t c_zstr)
{
    extern __shared__ __half smem[];

    const int tid  = threadIdx.x;
    const int lane = tid & 31;
    const int warp = tid >> 5;
    const int wm   = warp >> 2;   // 0..1 -> rows wm*64
    const int wn   = warp & 3;    // 0..3 -> cols wn*32

    const int z = blockIdx.z;
    const int e = z & (E_LOC - 1);

    const __half* Ab   = A    + (size_t)z * a_zstr + (size_t)blockIdx.y * BM * K;
    const __half* Bb   = Bw   + (size_t)e * b_estr + (size_t)blockIdx.x * BN * K;
    const float* biasb = bias + (size_t)e * bias_n + (size_t)blockIdx.x * BN;
    const size_t cbase = (size_t)z * c_zstr + (size_t)blockIdx.y * BM * ldc
                       + (size_t)blockIdx.x * BN;

    const uint32_t sb = smem_u32(smem);

    // ldmatrix lane addresses (byte offsets within a stage).
    // A x4 (per mt,ks): m0=rows r..r+7 @k0, m1=rows r+8..r+15 @k0, m2=r..r+7 @k8, m3=r+8.. @k8
    const int grp = lane >> 3;
    const uint32_t a_lane = ((uint32_t)(wm * 64 + (grp & 1) * 8 + (lane & 7)) * PAD_LD
                             + (grp >> 1) * 8) * 2;
    // B x4 (per nt-pair,ks): m0=(nt0,k0), m1=(nt0,k8), m2=(nt1,k0), m3=(nt1,k8)
    const uint32_t b_lane = ((uint32_t)(wn * 32 + (grp >> 1) * 8 + (lane & 7)) * PAD_LD
                             + (grp & 1) * 8) * 2;

    float acc[4][4][4];
#pragma unroll
    for (int mt = 0; mt < 4; mt++)
#pragma unroll
        for (int nt = 0; nt < 4; nt++)
#pragma unroll
            for (int i = 0; i < 4; i++) acc[mt][nt][i] = 0.0f;

    const int NK = K >> 5;

    load_stage(sb, 0, 0, Ab, Bb, K, tid); CP_COMMIT();
    load_stage(sb, 1, 1, Ab, Bb, K, tid); CP_COMMIT();

#pragma unroll 1
    for (int kt = 0; kt < NK; ++kt) {
        CP_WAIT1();                 // stage kt resident
        __syncthreads();            // all warps done reading the buffer being refilled

        if (kt + 2 < NK)
            load_stage(sb, (kt + 2) % 3, kt + 2, Ab, Bb, K, tid);
        CP_COMMIT();                // empty commit keeps group accounting uniform

        const uint32_t abase = sb + (uint32_t)(kt % 3) * STG_BYTES;
        const uint32_t bbase = abase + A_HALVES * 2;

#pragma unroll
        for (int ks = 0; ks < 2; ks++) {        // two K=16 steps per 32-K tile
            uint32_t af[4][4], bf[2][4];
#pragma unroll
            for (int mt = 0; mt < 4; mt++)
                ldsm_x4(af[mt], abase + a_lane + mt * (16 * PAD_LD * 2) + ks * 32);
#pragma unroll
            for (int p = 0; p < 2; p++)
                ldsm_x4(bf[p], bbase + b_lane + p * (16 * PAD_LD * 2) + ks * 32);

#pragma unroll
            for (int mt = 0; mt < 4; mt++)
#pragma unroll
                for (int nt = 0; nt < 4; nt++) {
                    const uint32_t b0 = bf[nt >> 1][(nt & 1) * 2 + 0];
                    const uint32_t b1 = bf[nt >> 1][(nt & 1) * 2 + 1];
                    asm volatile(
                        "mma.sync.aligned.m16n8k16.row.col.f32.f16.f16.f32 "
                        "{%0,%1,%2,%3},{%4,%5,%6,%7},{%8,%9},{%0,%1,%2,%3};"
                        : "+f"(acc[mt][nt][0]), "+f"(acc[mt][nt][1]),
                          "+f"(acc[mt][nt][2]), "+f"(acc[mt][nt][3])
                        : "r"(af[mt][0]), "r"(af[mt][1]), "r"(af[mt][2]), "r"(af[mt][3]),
                          "r"(b0), "r"(b1));
                }
        }
    }

    // ---------------- epilogue ----------------
#pragma unroll
    for (int mt = 0; mt < 4; mt++) {
        const int r0 = wm * 64 + mt * 16 + (lane >> 2);
#pragma unroll
        for (int nt = 0; nt < 4; nt++) {
            const int c0 = wn * 32 + nt * 8 + 2 * (lane & 3);
            const float b0 = biasb[c0];
            const float b1 = biasb[c0 + 1];
            float v0 = acc[mt][nt][0] + b0;
            float v1 = acc[mt][nt][1] + b1;
            float v2 = acc[mt][nt][2] + b0;
            float v3 = acc[mt][nt][3] + b1;
            if (GELU) {
                __half* Ch = (__half*)Cv + cbase;
                __half2 p0 = __floats2half2_rn(gelu_exact(v0), gelu_exact(v1));
                __half2 p1 = __floats2half2_rn(gelu_exact(v2), gelu_exact(v3));
                *reinterpret_cast<__half2*>(Ch + (size_t)r0 * ldc + c0)       = p0;
                *reinterpret_cast<__half2*>(Ch + (size_t)(r0 + 8) * ldc + c0) = p1;
            } else {
                float* Cf = (float*)Cv + cbase;
                *reinterpret_cast<float2*>(Cf + (size_t)r0 * ldc + c0)       = make_float2(v0, v1);
                *reinterpret_cast<float2*>(Cf + (size_t)(r0 + 8) * ldc + c0) = make_float2(v2, v3);
            }
        }
    }
}

// ---------------- prepass: fp32 -> fp16 (rn) ----------------
__global__ void f2h_kernel(const float4* __restrict__ in, uint4* __restrict__ out, size_t n8)
{
    size_t i = (size_t)blockIdx.x * blockDim.x + threadIdx.x;
    const size_t stride = (size_t)gridDim.x * blockDim.x;
    for (; i < n8; i += stride) {
        float4 a = in[2 * i];
        float4 b = in[2 * i + 1];
        uint4 o;
        o.x = h2_to_u32(__floats2half2_rn(a.x, a.y));
        o.y = h2_to_u32(__floats2half2_rn(a.z, a.w));
        o.z = h2_to_u32(__floats2half2_rn(b.x, b.y));
        o.w = h2_to_u32(__floats2half2_rn(b.z, b.w));
        out[i] = o;
    }
}

// ---------------- launch ----------------
extern "C" void kernel_launch(void* const* d_in, const int* in_sizes, int n_in,
                              void* d_out, int out_size)
{
    const float* x  = (const float*)d_in[0];  // [B, E*C, D]
    const float* w1 = (const float*)d_in[1];  // [E, F, D]
    const float* b1 = (const float*)d_in[2];  // [E, F]
    const float* w2 = (const float*)d_in[3];  // [E, D, F]
    const float* b2 = (const float*)d_in[4];  // [E, D]
    float* out = (float*)d_out;               // [B, E*C, D]

    __half *hid, *xh, *w1h, *w2h;
    cudaGetSymbolAddress((void**)&hid, g_hid);
    cudaGetSymbolAddress((void**)&xh,  g_xh);
    cudaGetSymbolAddress((void**)&w1h, g_w1h);
    cudaGetSymbolAddress((void**)&w2h, g_w2h);

    cudaFuncSetAttribute(gemm_nt_f16<true>,  cudaFuncAttributeMaxDynamicSharedMemorySize, SMEM_BYTES);
    cudaFuncSetAttribute(gemm_nt_f16<false>, cudaFuncAttributeMaxDynamicSharedMemorySize, SMEM_BYTES);

    const size_t nx = (size_t)B_DIM * E_LOC * C_CAP * D_MODEL;  // 32M
    const size_t nw = (size_t)E_LOC * D_FF * D_MODEL;           // 32M
    f2h_kernel<<<2048, 256>>>((const float4*)x,  (uint4*)xh,  nx / 8);
    f2h_kernel<<<2048, 256>>>((const float4*)w1, (uint4*)w1h, nw / 8);
    f2h_kernel<<<2048, 256>>>((const float4*)w2, (uint4*)w2h, nw / 8);

    const int ZB = B_DIM * E_LOC;  // 32

    // GEMM1: hid = half(gelu(x @ w1^T + b1))   M=1024, N=4096, K=1024
    {
        dim3 grid(D_FF / BN, C_CAP / BM, ZB);   // (32, 8, 32)
        gemm_nt_f16<true><<<grid, 256, SMEM_BYTES>>>(
            xh, w1h, b1, hid,
            /*K=*/D_MODEL, /*ldc=*/D_FF,
            /*a_zstr=*/(size_t)C_CAP * D_MODEL,
            /*b_estr=*/(size_t)D_FF * D_MODEL,
            /*bias_n=*/D_FF,
            /*c_zstr=*/(size_t)C_CAP * D_FF);
    }

    // GEMM2: out = hid @ w2^T + b2             M=1024, N=1024, K=4096
    {
        dim3 grid(D_MODEL / BN, C_CAP / BM, ZB);  // (8, 8, 32)
        gemm_nt_f16<false><<<grid, 256, SMEM_BYTES>>>(
            hid, w2h, b2, out,
            /*K=*/D_FF, /*ldc=*/D_MODEL,
            /*a_zstr=*/(size_t)C_CAP * D_FF,
            /*b_estr=*/(size_t)D_MODEL * D_FF,
            /*bias_n=*/D_MODEL,
            /*c_zstr=*/(size_t)C_CAP * D_MODEL);
    }
}

// round 16
// speedup vs baseline: 2.0523x; 1.0740x over previous
#include <cuda_runtime.h>
#include <cuda_fp16.h>
#include <cstdint>
#include <cstddef>

// ---------------- problem constants ----------------
#define E_LOC   8
#define B_DIM   4
#define C_CAP   1024
#define D_MODEL 1024
#define D_FF    4096

// ---------------- tile config ----------------
// fp16 HMMA m16n8k16, fp32 accum. Block 128x128x32, 128 threads = 4 warps
// (2M x 2N), warp tile 64x64 (acc 128 regs). ldmatrix feed, 4-stage cp.async,
// 2 CTAs/SM. HMMA:LDSM = 4:1.
#define BM 128
#define BN 128
#define BK 32
#define STAGES 4
#define THREADS 128

#define PAD_LD      40                      // halves per row (80B): LDSM conflict-free
#define A_HALVES    (BM * PAD_LD)           // 5120
#define B_HALVES    (BN * PAD_LD)           // 5120
#define STG_HALVES  (A_HALVES + B_HALVES)   // 10240
#define STG_BYTES   (STG_HALVES * 2)        // 20480
#define SMEM_BYTES  (STAGES * STG_BYTES)    // 81920

// ---------------- scratch (static __device__: no runtime alloc) ----------------
__device__ __half g_hid[(size_t)B_DIM * E_LOC * C_CAP * D_FF];     // 256 MB
__device__ __half g_xh [(size_t)B_DIM * E_LOC * C_CAP * D_MODEL];  // 64 MB
__device__ __half g_w1h[(size_t)E_LOC * D_FF * D_MODEL];           // 64 MB
__device__ __half g_w2h[(size_t)E_LOC * D_MODEL * D_FF];           // 64 MB

// ---------------- helpers ----------------
__device__ __forceinline__ uint32_t smem_u32(const void* p) {
    uint32_t a;
    asm("{ .reg .u64 t; cvta.to.shared.u64 t, %1; cvt.u32.u64 %0, t; }" : "=r"(a) : "l"(p));
    return a;
}
__device__ __forceinline__ void cp_async16(uint32_t saddr, const void* g) {
    asm volatile("cp.async.cg.shared.global [%0], [%1], 16;" :: "r"(saddr), "l"(g));
}
#define CP_COMMIT() asm volatile("cp.async.commit_group;" ::: "memory")
#define CP_WAIT2()  asm volatile("cp.async.wait_group 2;" ::: "memory")

__device__ __forceinline__ void ldsm_x4(uint32_t* r, uint32_t addr) {
    asm volatile("ldmatrix.sync.aligned.m8n8.x4.shared.b16 {%0,%1,%2,%3}, [%4];"
                 : "=r"(r[0]), "=r"(r[1]), "=r"(r[2]), "=r"(r[3]) : "r"(addr));
}
__device__ __forceinline__ float gelu_exact(float x) {
    return 0.5f * x * (1.0f + erff(x * 0.7071067811865476f));
}
__device__ __forceinline__ uint32_t h2_to_u32(__half2 h) {
    return *reinterpret_cast<uint32_t*>(&h);
}

// ---------------- stage loader: gmem(half) -> padded smem via cp.async ----------------
// A: 128 rows x 32 halves = 512 x 16B chunks / 128 thr = 4 per thread; B same.
__device__ __forceinline__ void load_stage(uint32_t sbase, int buf, int kt,
                                           const __half* __restrict__ Ab,
                                           const __half* __restrict__ Bb,
                                           int K, int tid)
{
    const int k0 = kt * BK;
    const uint32_t abase = sbase + (uint32_t)buf * STG_BYTES;
    const uint32_t bbase = abase + A_HALVES * 2;
    const int r0 = tid >> 2, j = tid & 3;           // base row, chunk
#pragma unroll
    for (int i = 0; i < 4; i++) {
        int r = r0 + i * 32;
        cp_async16(abase + r * (PAD_LD * 2) + j * 16, Ab + (size_t)r * K + k0 + j * 8);
    }
#pragma unroll
    for (int i = 0; i < 4; i++) {
        int r = r0 + i * 32;
        cp_async16(bbase + r * (PAD_LD * 2) + j * 16, Bb + (size_t)r * K + k0 + j * 8);
    }
}

// ---------------- grouped NT GEMM: C = A @ B^T (+bias)(+GELU) -----------------
// GELU=true writes __half hidden; GELU=false writes float.
template <bool GELU>
__global__ __launch_bounds__(THREADS, 2)
void gemm_nt_f16(const __half* __restrict__ A, const __half* __restrict__ Bw,
                 const float* __restrict__ bias, void* __restrict__ Cv,
                 int K, int ldc, size_t a_zstr, size_t b_estr, int bias_n, size_t c_zstr)
{
    extern __shared__ __half smem[];

    const int tid  = threadIdx.x;
    const int lane = tid & 31;
    const int warp = tid >> 5;
    const int wm   = warp & 1;    // rows wm*64
    const int wn   = warp >> 1;   // cols wn*64

    const int z = blockIdx.z;
    const int e = z & (E_LOC - 1);

    const __half* Ab   = A    + (size_t)z * a_zstr + (size_t)blockIdx.y * BM * K;
    const __half* Bb   = Bw   + (size_t)e * b_estr + (size_t)blockIdx.x * BN * K;
    const float* biasb = bias + (size_t)e * bias_n + (size_t)blockIdx.x * BN;
    const size_t cbase = (size_t)z * c_zstr + (size_t)blockIdx.y * BM * ldc
                       + (size_t)blockIdx.x * BN;

    const uint32_t sb = smem_u32(smem);

    // ldmatrix lane addresses (byte offsets within a stage).
    const int grp = lane >> 3;
    // A x4 per (mt,ks): rows [wm*64+mt*16, +16) x k16
    const uint32_t a_lane = ((uint32_t)(wm * 64 + (grp & 1) * 8 + (lane & 7)) * PAD_LD
                             + (grp >> 1) * 8) * 2;
    // B x4 per (p,ks): cols [wn*64+p*16, +16) x k16   (p = nt pair)
    const uint32_t b_lane = ((uint32_t)(wn * 64 + (grp >> 1) * 8 + (lane & 7)) * PAD_LD
                             + (grp & 1) * 8) * 2;

    float acc[4][8][4];
#pragma unroll
    for (int mt = 0; mt < 4; mt++)
#pragma unroll
        for (int nt = 0; nt < 8; nt++)
#pragma unroll
            for (int i = 0; i < 4; i++) acc[mt][nt][i] = 0.0f;

    const int NK = K >> 5;

    load_stage(sb, 0, 0, Ab, Bb, K, tid); CP_COMMIT();
    load_stage(sb, 1, 1, Ab, Bb, K, tid); CP_COMMIT();
    load_stage(sb, 2, 2, Ab, Bb, K, tid); CP_COMMIT();

#pragma unroll 1
    for (int kt = 0; kt < NK; ++kt) {
        CP_WAIT2();                 // stage kt resident
        __syncthreads();            // all warps done reading buffer being refilled

        if (kt + 3 < NK)
            load_stage(sb, (kt + 3) & 3, kt + 3, Ab, Bb, K, tid);
        CP_COMMIT();                // empty commit keeps group accounting uniform

        const uint32_t abase = sb + (uint32_t)(kt & 3) * STG_BYTES;
        const uint32_t bbase = abase + A_HALVES * 2;

#pragma unroll
        for (int ks = 0; ks < 2; ks++) {        // two K=16 steps per 32-K tile
            uint32_t af[4][4], bf[4][4];
#pragma unroll
            for (int mt = 0; mt < 4; mt++)
                ldsm_x4(af[mt], abase + a_lane + mt * (16 * PAD_LD * 2) + ks * 32);
#pragma unroll
            for (int p = 0; p < 4; p++)
                ldsm_x4(bf[p], bbase + b_lane + p * (16 * PAD_LD * 2) + ks * 32);

#pragma unroll
            for (int mt = 0; mt < 4; mt++)
#pragma unroll
                for (int nt = 0; nt < 8; nt++) {
                    const uint32_t b0 = bf[nt >> 1][(nt & 1) * 2 + 0];
                    const uint32_t b1 = bf[nt >> 1][(nt & 1) * 2 + 1];
                    asm volatile(
                        "mma.sync.aligned.m16n8k16.row.col.f32.f16.f16.f32 "
                        "{%0,%1,%2,%3},{%4,%5,%6,%7},{%8,%9},{%0,%1,%2,%3};"
                        : "+f"(acc[mt][nt][0]), "+f"(acc[mt][nt][1]),
                          "+f"(acc[mt][nt][2]), "+f"(acc[mt][nt][3])
                        : "r"(af[mt][0]), "r"(af[mt][1]), "r"(af[mt][2]), "r"(af[mt][3]),
                          "r"(b0), "r"(b1));
                }
        }
    }

    // ---------------- epilogue ----------------
#pragma unroll
    for (int mt = 0; mt < 4; mt++) {
        const int r0 = wm * 64 + mt * 16 + (lane >> 2);
#pragma unroll
        for (int nt = 0; nt < 8; nt++) {
            const int c0 = wn * 64 + nt * 8 + 2 * (lane & 3);
            const float b0 = biasb[c0];
            const float b1 = biasb[c0 + 1];
            float v0 = acc[mt][nt][0] + b0;
            float v1 = acc[mt][nt][1] + b1;
            float v2 = acc[mt][nt][2] + b0;
            float v3 = acc[mt][nt][3] + b1;
            if (GELU) {
                __half* Ch = (__half*)Cv + cbase;
                __half2 p0 = __floats2half2_rn(gelu_exact(v0), gelu_exact(v1));
                __half2 p1 = __floats2half2_rn(gelu_exact(v2), gelu_exact(v3));
                *reinterpret_cast<__half2*>(Ch + (size_t)r0 * ldc + c0)       = p0;
                *reinterpret_cast<__half2*>(Ch + (size_t)(r0 + 8) * ldc + c0) = p1;
            } else {
                float* Cf = (float*)Cv + cbase;
                *reinterpret_cast<float2*>(Cf + (size_t)r0 * ldc + c0)       = make_float2(v0, v1);
                *reinterpret_cast<float2*>(Cf + (size_t)(r0 + 8) * ldc + c0) = make_float2(v2, v3);
            }
        }
    }
}

// ---------------- prepass: fp32 -> fp16 (rn) ----------------
__global__ void f2h_kernel(const float4* __restrict__ in, uint4* __restrict__ out, size_t n8)
{
    size_t i = (size_t)blockIdx.x * blockDim.x + threadIdx.x;
    const size_t stride = (size_t)gridDim.x * blockDim.x;
    for (; i < n8; i += stride) {
        float4 a = in[2 * i];
        float4 b = in[2 * i + 1];
        uint4 o;
        o.x = h2_to_u32(__floats2half2_rn(a.x, a.y));
        o.y = h2_to_u32(__floats2half2_rn(a.z, a.w));
        o.z = h2_to_u32(__floats2half2_rn(b.x, b.y));
        o.w = h2_to_u32(__floats2half2_rn(b.z, b.w));
        out[i] = o;
    }
}

// ---------------- launch ----------------
extern "C" void kernel_launch(void* const* d_in, const int* in_sizes, int n_in,
                              void* d_out, int out_size)
{
    const float* x  = (const float*)d_in[0];  // [B, E*C, D]
    const float* w1 = (const float*)d_in[1];  // [E, F, D]
    const float* b1 = (const float*)d_in[2];  // [E, F]
    const float* w2 = (const float*)d_in[3];  // [E, D, F]
    const float* b2 = (const float*)d_in[4];  // [E, D]
    float* out = (float*)d_out;               // [B, E*C, D]

    __half *hid, *xh, *w1h, *w2h;
    cudaGetSymbolAddress((void**)&hid, g_hid);
    cudaGetSymbolAddress((void**)&xh,  g_xh);
    cudaGetSymbolAddress((void**)&w1h, g_w1h);
    cudaGetSymbolAddress((void**)&w2h, g_w2h);

    cudaFuncSetAttribute(gemm_nt_f16<true>,  cudaFuncAttributeMaxDynamicSharedMemorySize, SMEM_BYTES);
    cudaFuncSetAttribute(gemm_nt_f16<false>, cudaFuncAttributeMaxDynamicSharedMemorySize, SMEM_BYTES);

    const size_t nx = (size_t)B_DIM * E_LOC * C_CAP * D_MODEL;  // 32M
    const size_t nw = (size_t)E_LOC * D_FF * D_MODEL;           // 32M
    f2h_kernel<<<2048, 256>>>((const float4*)x,  (uint4*)xh,  nx / 8);
    f2h_kernel<<<2048, 256>>>((const float4*)w1, (uint4*)w1h, nw / 8);
    f2h_kernel<<<2048, 256>>>((const float4*)w2, (uint4*)w2h, nw / 8);

    const int ZB = B_DIM * E_LOC;  // 32

    // GEMM1: hid = half(gelu(x @ w1^T + b1))   M=1024, N=4096, K=1024
    {
        dim3 grid(D_FF / BN, C_CAP / BM, ZB);   // (32, 8, 32)
        gemm_nt_f16<true><<<grid, THREADS, SMEM_BYTES>>>(
            xh, w1h, b1, hid,
            /*K=*/D_MODEL, /*ldc=*/D_FF,
            /*a_zstr=*/(size_t)C_CAP * D_MODEL,
            /*b_estr=*/(size_t)D_FF * D_MODEL,
            /*bias_n=*/D_FF,
            /*c_zstr=*/(size_t)C_CAP * D_FF);
    }

    // GEMM2: out = hid @ w2^T + b2             M=1024, N=1024, K=4096
    {
        dim3 grid(D_MODEL / BN, C_CAP / BM, ZB);  // (8, 8, 32)
        gemm_nt_f16<false><<<grid, THREADS, SMEM_BYTES>>>(
            hid, w2h, b2, out,
            /*K=*/D_FF, /*ldc=*/D_MODEL,
            /*a_zstr=*/(size_t)C_CAP * D_FF,
            /*b_estr=*/(size_t)D_MODEL * D_FF,
            /*bias_n=*/D_MODEL,
            /*c_zstr=*/(size_t)C_CAP * D_MODEL);
    }
}